// round 10
// baseline (speedup 1.0000x reference)
#include <cuda_runtime.h>
#include <math.h>
#include <stdint.h>

#define NB 2
#define NL 2048
#define ND 1024
#define NH 16
#define NDH 64
#define MROWS (NB*NL)   // 4096
#define HID (4*ND)      // 4096

// ---------------- scratch ----------------
__device__ float g_h  [(size_t)MROWS * HID];
__device__ float g_q  [(size_t)NB*NH*NL*NDH];
__device__ float g_k  [(size_t)NB*NH*NL*NDH];
__device__ float g_v  [(size_t)NB*NH*NL*NDH];
__device__ float g_ym [(size_t)MROWS * ND];
__device__ float g_z  [(size_t)MROWS * ND];
__device__ float g_pos[NB*NL];

__device__ __forceinline__ float silu_f(float x){ return x / (1.0f + expf(-x)); }

__device__ __forceinline__ uint32_t tf32_bits(float x){
    uint32_t u; asm("cvt.rna.tf32.f32 %0, %1;" : "=r"(u) : "f"(x));
    return u;
}
__device__ __forceinline__ float tf32_rnd(float x){ return __uint_as_float(tf32_bits(x)); }

__device__ __forceinline__ uint32_t smem_u32(const void* p){
    uint32_t a;
    asm("{ .reg .u64 t; cvta.to.shared.u64 t, %1; cvt.u32.u64 %0, t; }" : "=r"(a) : "l"(p));
    return a;
}
__device__ __forceinline__ void cp_async16(uint32_t saddr, const void* g){
    asm volatile("cp.async.cg.shared.global [%0], [%1], 16;" :: "r"(saddr), "l"(g));
}
#define CP_COMMIT()  asm volatile("cp.async.commit_group;" ::: "memory")
#define CP_WAIT(n)   asm volatile("cp.async.wait_group %0;" :: "n"(n) : "memory")

#define MMA16N8K8(c, a, b) \
    asm volatile("mma.sync.aligned.m16n8k8.row.col.f32.tf32.tf32.f32 " \
        "{%0,%1,%2,%3}, {%4,%5,%6,%7}, {%8,%9}, {%0,%1,%2,%3};" \
        : "+f"((c)[0]), "+f"((c)[1]), "+f"((c)[2]), "+f"((c)[3]) \
        : "r"((a)[0]), "r"((a)[1]), "r"((a)[2]), "r"((a)[3]), \
          "r"((b)[0]), "r"((b)[1]))

// ---------------- 1. cumsum of rope_lambda -> g_pos ----------------
__global__ void cumsum_kernel(const float* __restrict__ rl)
{
    __shared__ float s[1024];
    int b = blockIdx.x, t = threadIdx.x;
    const float* a = rl + (size_t)b * NL;
    float x0 = a[2*t], x1 = a[2*t+1];
    float sum = x0 + x1;
    s[t] = sum;
    __syncthreads();
    for (int off = 1; off < 1024; off <<= 1){
        float v = (t >= off) ? s[t-off] : 0.0f;
        __syncthreads();
        s[t] += v;
        __syncthreads();
    }
    float incl = s[t];
    g_pos[b*NL + 2*t]     = incl - x1;
    g_pos[b*NL + 2*t + 1] = incl;
}

// ---------------- 2/5. tf32 mma.sync GEMM (NT), 3-stage ----------------
#define GSTAGES 3
#define GKC 32
#define G_STRIDE 36
#define G_TILE_F (128*G_STRIDE)
#define G_TILE_B (G_TILE_F*4)
#define G_SMEM_BYTES (GSTAGES * 2 * G_TILE_B)   // 110592

template<int EPI>
__global__ void __launch_bounds__(256, 2)
gemm_mma(const float* __restrict__ A, const float* __restrict__ Bw,
         const float* __restrict__ bias, const float* __restrict__ resid,
         float* __restrict__ C, int N, int K)
{
    extern __shared__ float dsm[];
    const uint32_t sb = smem_u32(dsm);
    const int tid  = threadIdx.x;
    const int lane = tid & 31, wid = tid >> 5;
    const int wm = wid >> 2, wn = wid & 3;
    const int g  = lane >> 2, t = lane & 3;
    const int bn = blockIdx.x * 128;
    const int bm = blockIdx.y * 128;

    float acc[4][4][4];
    #pragma unroll
    for (int i = 0; i < 4; i++)
        #pragma unroll
        for (int j = 0; j < 4; j++)
            #pragma unroll
            for (int c = 0; c < 4; c++) acc[i][j][c] = 0.0f;

    auto load_stage = [&](int s, int kt){
        uint32_t base = sb + (uint32_t)s * (2*G_TILE_B);
        #pragma unroll
        for (int it = 0; it < 8; it++){
            int idx = tid + it*256;
            int isB = idx >> 10;
            int li  = idx & 1023;
            int row = li >> 3;
            int c16 = li & 7;
            const float* src = (isB ? (Bw + (size_t)(bn+row)*K)
                                    : (A  + (size_t)(bm+row)*K)) + kt + c16*4;
            cp_async16(base + (uint32_t)isB*G_TILE_B + (uint32_t)(row*144 + c16*16), src);
        }
        CP_COMMIT();
    };

    #pragma unroll
    for (int s = 0; s < GSTAGES; s++) load_stage(s, s*GKC);

    const int NCH = K / GKC;
    int s = 0;
    for (int ch = 0; ch < NCH; ch++){
        CP_WAIT(GSTAGES-1);
        __syncthreads();

        const float* As = dsm + (size_t)s*2*G_TILE_F;
        const float* Bs = As + G_TILE_F;
        const float* Awp = As + (wm*64 + g)*G_STRIDE + t;
        const float* Bwp = Bs + (wn*32 + g)*G_STRIDE + t;

        #pragma unroll
        for (int ks = 0; ks < 4; ks++){
            int k0 = ks*8;
            uint32_t b[4][2];
            #pragma unroll
            for (int fj = 0; fj < 4; fj++){
                const float* bp = Bwp + fj*8*G_STRIDE + k0;
                b[fj][0] = tf32_bits(bp[0]);
                b[fj][1] = tf32_bits(bp[4]);
            }
            #pragma unroll
            for (int fi = 0; fi < 4; fi++){
                const float* ap = Awp + fi*16*G_STRIDE + k0;
                uint32_t a[4];
                a[0] = tf32_bits(ap[0]);
                a[1] = tf32_bits(ap[8*G_STRIDE]);
                a[2] = tf32_bits(ap[4]);
                a[3] = tf32_bits(ap[8*G_STRIDE+4]);
                #pragma unroll
                for (int fj = 0; fj < 4; fj++)
                    MMA16N8K8(acc[fi][fj], a, b[fj]);
            }
        }
        __syncthreads();
        if (ch + GSTAGES < NCH) load_stage(s, (ch + GSTAGES)*GKC);
        if (++s == GSTAGES) s = 0;
    }

    #pragma unroll
    for (int fi = 0; fi < 4; fi++){
        int m0 = bm + wm*64 + fi*16 + g;
        #pragma unroll
        for (int fj = 0; fj < 4; fj++){
            int n = bn + wn*32 + fj*8 + 2*t;
            float2 bv = *(const float2*)(bias + n);
            float2 o0, o1;
            o0.x = acc[fi][fj][0] + bv.x; o0.y = acc[fi][fj][1] + bv.y;
            o1.x = acc[fi][fj][2] + bv.x; o1.y = acc[fi][fj][3] + bv.y;
            if (EPI == 0){
                o0.x = silu_f(o0.x); o0.y = silu_f(o0.y);
                o1.x = silu_f(o1.x); o1.y = silu_f(o1.y);
            } else {
                float2 r0 = *(const float2*)(resid + (size_t)m0*N + n);
                float2 r1 = *(const float2*)(resid + (size_t)(m0+8)*N + n);
                o0.x += r0.x; o0.y += r0.y;
                o1.x += r1.x; o1.y += r1.y;
            }
            *(float2*)(C + (size_t)m0*N + n)     = o0;
            *(float2*)(C + (size_t)(m0+8)*N + n) = o1;
        }
    }
}

// ---------------- 3. RoPE + gates + head transpose (tf32 pre-round) ----------------
__global__ void rope_gate_kernel(const float* __restrict__ qg,
                                 const float* __restrict__ kg,
                                 const float* __restrict__ vg)
{
    int tid = blockIdx.x * blockDim.x + threadIdx.x;
    int d  = tid & 31;
    int hh = (tid >> 5) & 15;
    int l  = (tid >> 9) & 2047;
    int b  = tid >> 20;
    if (b >= NB) return;
    size_t row   = (size_t)b*NL + l;
    size_t hbase = row * HID;
    float p   = g_pos[row];
    float inv = expf(-(float)d * (9.210340371976184f / 32.0f));
    float fr  = p * inv;
    float sn, cs;
    sincosf(fr, &sn, &cs);
    size_t ob = (((size_t)b*NH + hh)*NL + l)*NDH;
    {
        float2 e = *(const float2*)(&g_h[hbase + 2*ND + hh*NDH + 2*d]);
        float gq = qg[row*NH + hh];
        g_q[ob + d]      = tf32_rnd((e.x*cs - e.y*sn) * gq);
        g_q[ob + d + 32] = tf32_rnd((e.x*sn + e.y*cs) * gq);
    }
    {
        float2 e = *(const float2*)(&g_h[hbase + 3*ND + hh*NDH + 2*d]);
        float gk = kg[row*NH + hh];
        g_k[ob + d]      = tf32_rnd((e.x*cs - e.y*sn) * gk);
        g_k[ob + d + 32] = tf32_rnd((e.x*sn + e.y*cs) * gk);
    }
    {
        float gv = vg[row*NH + hh];
        g_v[ob + d]      = tf32_rnd(g_h[hbase + ND + hh*NDH + d]      * gv);
        g_v[ob + d + 32] = tf32_rnd(g_h[hbase + ND + hh*NDH + d + 32] * gv);
    }
}

// ---------------- 4. tf32 mma attention v3 ----------------
// CTA: 64 q-rows for one (b,h); 8 warps. 3-slot KV ring (2-ahead prefetch).
// QK^T: warp w -> m-rows (w>>1)*16, key-half (w&1)*16. Q frags in regs.
// S@V : same m-rows, d-half (w&1)*32. S round-trip synced per warp PAIR (bar.sync).
// smem: Q region (reused as S) + 3 KV slots = 69632 B -> 3 CTAs/SM.
#define AST 68
#define SST 36
#define ABK 32
#define A_KV_F (2*ABK*AST)                 // floats per KV slot
#define A_QS_F (64*AST)
#define A_SMEM_BYTES ((A_QS_F + 3*A_KV_F)*4)   // 69632

__global__ void __launch_bounds__(256, 3)
attn_mma(const float* __restrict__ bias, const float* __restrict__ head_scale)
{
    extern __shared__ float sm[];
    float* Qs = sm;                    // [64][AST], later reused as Ss [64][SST]
    float* Ss = sm;
    float* KV = sm + A_QS_F;           // [3][{K,V}][ABK][AST]

    const int ib = (int)gridDim.x - 1 - (int)blockIdx.x;   // big tiles first
    const int bh = blockIdx.y;
    const int b  = bh >> 4, hh = bh & 15;
    const int tid = threadIdx.x, lane = tid & 31, wid = tid >> 5;
    const int g = lane >> 2, t = lane & 3;
    const int r0 = (wid >> 1) * 16;        // warp m-rows
    const int kh = (wid & 1);              // key-half / d-half selector
    const int pair_bar = 1 + (wid >> 1);   // named barrier per warp pair

    const int njb = 2*(ib + 1);

    auto load_kv = [&](int slot, int jb){
        if (jb < njb){
            float* Ks = KV + slot*A_KV_F;
            float* Vs = Ks + ABK*AST;
            const float* kp = g_k + ((size_t)bh*NL + (size_t)jb*ABK)*NDH;
            const float* vp = g_v + ((size_t)bh*NL + (size_t)jb*ABK)*NDH;
            #pragma unroll
            for (int it = 0; it < 4; it++){
                int idx = tid + it*256;      // 0..1023
                int isV = idx >> 9;
                int li  = idx & 511;
                int row = li >> 4;
                int c16 = li & 15;
                float* dst = (isV ? Vs : Ks) + row*AST + c16*4;
                const float* src = (isV ? vp : kp) + row*64 + c16*4;
                cp_async16(smem_u32(dst), src);
            }
        }
        CP_COMMIT();
    };

    {   // group 0: Q tile (64 rows x 16 chunks)
        const float* qp = g_q + ((size_t)bh*NL + (size_t)ib*64)*NDH;
        #pragma unroll
        for (int it = 0; it < 4; it++){
            int idx = tid + it*256;
            int row = idx >> 4;
            int c16 = idx & 15;
            cp_async16(smem_u32(Qs + row*AST + c16*4), qp + row*64 + c16*4);
        }
        CP_COMMIT();
    }
    load_kv(0, 0);      // group 1
    load_kv(1, 1);      // group 2

    // wait for Q (group0); hoist Q fragments to registers
    CP_WAIT(2);
    __syncthreads();
    uint32_t Qa[8][4];
    {
        const float* qw = Qs + (r0 + g)*AST + t;
        #pragma unroll
        for (int ks = 0; ks < 8; ks++){
            Qa[ks][0] = __float_as_uint(qw[ks*8]);
            Qa[ks][1] = __float_as_uint(qw[8*AST + ks*8]);
            Qa[ks][2] = __float_as_uint(qw[ks*8 + 4]);
            Qa[ks][3] = __float_as_uint(qw[8*AST + ks*8 + 4]);
        }
    }
    __syncthreads();    // all warps done reading Q before S region reuse

    const float scale = head_scale[hh];
    float Yc[4][4];
    #pragma unroll
    for (int j = 0; j < 4; j++)
        #pragma unroll
        for (int c = 0; c < 4; c++) Yc[j][c] = 0.0f;

    const int ig0 = ib*64 + r0 + g;

    for (int jb = 0; jb < njb; ++jb){
        int slot;
        { int m3 = jb % 3; slot = m3; }
        CP_WAIT(1);
        __syncthreads();                       // slot ready; prev iter fully done
        load_kv((jb + 2) % 3, jb + 2);         // refill (empty commit if beyond)

        // bias prefetch (latency hidden under QK mma loop)
        float2 pb0[2], pb1[2];
        {
            const float* bp = bias + ((size_t)b*NL + ig0)*NL + jb*ABK + kh*16 + 2*t;
            #pragma unroll
            for (int nf = 0; nf < 2; nf++){
                pb0[nf] = *(const float2*)(bp + nf*8);
                pb1[nf] = *(const float2*)(bp + nf*8 + (size_t)8*NL);
            }
        }

        const float* Ksb = KV + slot*A_KV_F;
        const float* Vsb = Ksb + ABK*AST;

        // ---- S = Q @ K^T  (keys kh*16 .. kh*16+15) ----
        float Sc[2][4];
        #pragma unroll
        for (int nf = 0; nf < 2; nf++)
            #pragma unroll
            for (int c = 0; c < 4; c++) Sc[nf][c] = 0.0f;

        const float* Bw = Ksb + (kh*16 + g)*AST + t;
        #pragma unroll
        for (int ks = 0; ks < 8; ks++){
            #pragma unroll
            for (int nf = 0; nf < 2; nf++){
                uint32_t bf[2];
                bf[0] = __float_as_uint(Bw[nf*8*AST + ks*8]);
                bf[1] = __float_as_uint(Bw[nf*8*AST + ks*8 + 4]);
                MMA16N8K8(Sc[nf], Qa[ks], bf);
            }
        }

        // ---- epilogue: scale + 4*bias + silu + causal -> Ss ----
        #pragma unroll
        for (int nf = 0; nf < 2; nf++){
            int lc = kh*16 + nf*8 + 2*t;
            int jg = jb*ABK + lc;
            float z00 = silu_f(fmaf(Sc[nf][0], scale, 4.0f*pb0[nf].x));
            float z01 = silu_f(fmaf(Sc[nf][1], scale, 4.0f*pb0[nf].y));
            float z10 = silu_f(fmaf(Sc[nf][2], scale, 4.0f*pb1[nf].x));
            float z11 = silu_f(fmaf(Sc[nf][3], scale, 4.0f*pb1[nf].y));
            if (jg     > ig0    ) z00 = 0.0f;
            if (jg + 1 > ig0    ) z01 = 0.0f;
            if (jg     > ig0 + 8) z10 = 0.0f;
            if (jg + 1 > ig0 + 8) z11 = 0.0f;
            float2 s0, s1;
            s0.x = tf32_rnd(z00); s0.y = tf32_rnd(z01);
            s1.x = tf32_rnd(z10); s1.y = tf32_rnd(z11);
            *(float2*)&Ss[(r0+g)*SST + lc]   = s0;
            *(float2*)&Ss[(r0+8+g)*SST + lc] = s1;
        }
        // pair-scoped barrier: only the 2 warps sharing rows r0..r0+15 exchange S
        asm volatile("bar.sync %0, %1;" :: "r"(pair_bar), "r"(64) : "memory");

        // ---- Y += S @ V  (d-cols kh*32 .. kh*32+31) ----
        const float* Aw2 = Ss + (r0 + g)*SST + t;
        #pragma unroll
        for (int ks = 0; ks < 4; ks++){
            uint32_t a[4];
            a[0] = __float_as_uint(Aw2[ks*8]);
            a[1] = __float_as_uint(Aw2[8*SST + ks*8]);
            a[2] = __float_as_uint(Aw2[ks*8 + 4]);
            a[3] = __float_as_uint(Aw2[8*SST + ks*8 + 4]);
            #pragma unroll
            for (int nf = 0; nf < 4; nf++){
                int dc = kh*32 + nf*8 + g;
                uint32_t bf[2];
                bf[0] = __float_as_uint(Vsb[(ks*8 + t)*AST + dc]);
                bf[1] = __float_as_uint(Vsb[(ks*8 + t + 4)*AST + dc]);
                MMA16N8K8(Yc[nf], a, bf);
            }
        }
    }

    // ---- final: ym = Y * u ----
    {
        int l = ib*64 + r0 + g;
        size_t row0 = (size_t)b*NL + l;
        #pragma unroll
        for (int nf = 0; nf < 4; nf++){
            int d0 = kh*32 + nf*8 + 2*t;
            float2 u0 = *(const float2*)&g_h[row0*HID + hh*NDH + d0];
            float2 u1 = *(const float2*)&g_h[(row0+8)*HID + hh*NDH + d0];
            float2 o0, o1;
            o0.x = Yc[nf][0]*u0.x; o0.y = Yc[nf][1]*u0.y;
            o1.x = Yc[nf][2]*u1.x; o1.y = Yc[nf][3]*u1.y;
            *(float2*)&g_ym[row0*ND + hh*NDH + d0]     = o0;
            *(float2*)&g_ym[(row0+8)*ND + hh*NDH + d0] = o1;
        }
    }
}

// ---------------- 6. LayerNorm ----------------
__global__ void ln_kernel(const float* __restrict__ z, const float* __restrict__ gamma,
                          const float* __restrict__ beta, float* __restrict__ out)
{
    __shared__ float rs[8], rq[8], mv[2];
    int row = blockIdx.x;
    int t = threadIdx.x;
    const float4* zr = (const float4*)(z + (size_t)row * ND);
    float4 v = zr[t];
    float s  = v.x + v.y + v.z + v.w;
    float sq = v.x*v.x + v.y*v.y + v.z*v.z + v.w*v.w;
    #pragma unroll
    for (int o = 16; o; o >>= 1){
        s  += __shfl_down_sync(0xffffffffu, s,  o);
        sq += __shfl_down_sync(0xffffffffu, sq, o);
    }
    if ((t & 31) == 0){ rs[t>>5] = s; rq[t>>5] = sq; }
    __syncthreads();
    if (t == 0){
        float S = 0.f, Q = 0.f;
        #pragma unroll
        for (int i = 0; i < 8; i++){ S += rs[i]; Q += rq[i]; }
        float mean = S * (1.0f/ND);
        float var  = Q * (1.0f/ND) - mean*mean;
        mv[0] = mean; mv[1] = rsqrtf(var + 1e-5f);
    }
    __syncthreads();
    float mean = mv[0], rstd = mv[1];
    float4 g  = ((const float4*)gamma)[t];
    float4 be = ((const float4*)beta )[t];
    float4 o;
    o.x = (v.x - mean)*rstd*g.x + be.x;
    o.y = (v.y - mean)*rstd*g.y + be.y;
    o.z = (v.z - mean)*rstd*g.z + be.z;
    o.w = (v.w - mean)*rstd*g.w + be.w;
    ((float4*)(out + (size_t)row * ND))[t] = o;
}

// ---------------- launch ----------------
extern "C" void kernel_launch(void* const* d_in, const int* in_sizes, int n_in,
                              void* d_out, int out_size)
{
    const float* x   = (const float*)d_in[0];
    const float* rl  = (const float*)d_in[3];
    const float* qg  = (const float*)d_in[4];
    const float* kg  = (const float*)d_in[5];
    const float* vg  = (const float*)d_in[6];
    const float* tpb = (const float*)d_in[7];
    const float* pw  = (const float*)d_in[8];
    const float* pb  = (const float*)d_in[9];
    const float* ow  = (const float*)d_in[10];
    const float* ob  = (const float*)d_in[11];
    const float* hs  = (const float*)d_in[12];
    const float* lg  = (const float*)d_in[13];
    const float* lb  = (const float*)d_in[14];
    float* out = (float*)d_out;

    float *hp, *ymp, *zp;
    cudaGetSymbolAddress((void**)&hp,  g_h);
    cudaGetSymbolAddress((void**)&ymp, g_ym);
    cudaGetSymbolAddress((void**)&zp,  g_z);

    cudaFuncSetAttribute(gemm_mma<0>, cudaFuncAttributeMaxDynamicSharedMemorySize, G_SMEM_BYTES);
    cudaFuncSetAttribute(gemm_mma<1>, cudaFuncAttributeMaxDynamicSharedMemorySize, G_SMEM_BYTES);
    cudaFuncSetAttribute(attn_mma,    cudaFuncAttributeMaxDynamicSharedMemorySize, A_SMEM_BYTES);

    // 1. positions
    cumsum_kernel<<<NB, 1024>>>(rl);

    // 2. h = silu(x @ proj_w^T + proj_b)   [tf32 mma]
    gemm_mma<0><<<dim3(HID/128, MROWS/128), 256, G_SMEM_BYTES>>>(x, pw, pb, nullptr, hp, HID, ND);

    // 3. rope + gates + head transpose (+ tf32 pre-round of q/k/v)
    rope_gate_kernel<<<(NB*NL*NH*32)/256, 256>>>(qg, kg, vg);

    // 4. fused attention + u-gate   [tf32 mma]
    attn_mma<<<dim3(NL/64, NB*NH), 256, A_SMEM_BYTES>>>(tpb, hs);

    // 5. z = ym @ out_w^T + out_b + x   [tf32 mma]
    gemm_mma<1><<<dim3(ND/128, MROWS/128), 256, G_SMEM_BYTES>>>(ymp, ow, ob, x, zp, ND, ND);

    // 6. layernorm
    ln_kernel<<<MROWS, 256>>>(zp, lg, lb, out);
}

// round 11
// speedup vs baseline: 1.4885x; 1.4885x over previous
#include <cuda_runtime.h>
#include <math.h>
#include <stdint.h>

#define NB 2
#define NL 2048
#define ND 1024
#define NH 16
#define NDH 64
#define MROWS (NB*NL)   // 4096
#define HID (4*ND)      // 4096

// ---------------- scratch ----------------
__device__ float g_h  [(size_t)MROWS * HID];
__device__ float g_q  [(size_t)NB*NH*NL*NDH];
__device__ float g_k  [(size_t)NB*NH*NL*NDH];
__device__ float g_v  [(size_t)NB*NH*NL*NDH];
__device__ float g_ym [(size_t)MROWS * ND];
__device__ float g_z  [(size_t)MROWS * ND];
__device__ float g_pos[NB*NL];

__device__ __forceinline__ float silu_f(float x){ return x / (1.0f + expf(-x)); }

__device__ __forceinline__ uint32_t tf32_bits(float x){
    uint32_t u; asm("cvt.rna.tf32.f32 %0, %1;" : "=r"(u) : "f"(x));
    return u;
}
__device__ __forceinline__ float tf32_rnd(float x){ return __uint_as_float(tf32_bits(x)); }

__device__ __forceinline__ uint32_t smem_u32(const void* p){
    uint32_t a;
    asm("{ .reg .u64 t; cvta.to.shared.u64 t, %1; cvt.u32.u64 %0, t; }" : "=r"(a) : "l"(p));
    return a;
}
__device__ __forceinline__ void cp_async16(uint32_t saddr, const void* g){
    asm volatile("cp.async.cg.shared.global [%0], [%1], 16;" :: "r"(saddr), "l"(g));
}
#define CP_COMMIT()  asm volatile("cp.async.commit_group;" ::: "memory")
#define CP_WAIT(n)   asm volatile("cp.async.wait_group %0;" :: "n"(n) : "memory")

#define MMA16N8K8(c, a, b) \
    asm volatile("mma.sync.aligned.m16n8k8.row.col.f32.tf32.tf32.f32 " \
        "{%0,%1,%2,%3}, {%4,%5,%6,%7}, {%8,%9}, {%0,%1,%2,%3};" \
        : "+f"((c)[0]), "+f"((c)[1]), "+f"((c)[2]), "+f"((c)[3]) \
        : "r"((a)[0]), "r"((a)[1]), "r"((a)[2]), "r"((a)[3]), \
          "r"((b)[0]), "r"((b)[1]))

// ---------------- 1. cumsum of rope_lambda -> g_pos ----------------
__global__ void cumsum_kernel(const float* __restrict__ rl)
{
    __shared__ float s[1024];
    int b = blockIdx.x, t = threadIdx.x;
    const float* a = rl + (size_t)b * NL;
    float x0 = a[2*t], x1 = a[2*t+1];
    float sum = x0 + x1;
    s[t] = sum;
    __syncthreads();
    for (int off = 1; off < 1024; off <<= 1){
        float v = (t >= off) ? s[t-off] : 0.0f;
        __syncthreads();
        s[t] += v;
        __syncthreads();
    }
    float incl = s[t];
    g_pos[b*NL + 2*t]     = incl - x1;
    g_pos[b*NL + 2*t + 1] = incl;
}

// ---------------- 2/5. tf32 mma.sync GEMM (NT), 3-stage ----------------
#define GSTAGES 3
#define GKC 32
#define G_STRIDE 36
#define G_TILE_F (128*G_STRIDE)
#define G_TILE_B (G_TILE_F*4)
#define G_SMEM_BYTES (GSTAGES * 2 * G_TILE_B)   // 110592

template<int EPI>
__global__ void __launch_bounds__(256, 2)
gemm_mma(const float* __restrict__ A, const float* __restrict__ Bw,
         const float* __restrict__ bias, const float* __restrict__ resid,
         float* __restrict__ C, int N, int K)
{
    extern __shared__ float dsm[];
    const uint32_t sb = smem_u32(dsm);
    const int tid  = threadIdx.x;
    const int lane = tid & 31, wid = tid >> 5;
    const int wm = wid >> 2, wn = wid & 3;
    const int g  = lane >> 2, t = lane & 3;
    const int bn = blockIdx.x * 128;
    const int bm = blockIdx.y * 128;

    float acc[4][4][4];
    #pragma unroll
    for (int i = 0; i < 4; i++)
        #pragma unroll
        for (int j = 0; j < 4; j++)
            #pragma unroll
            for (int c = 0; c < 4; c++) acc[i][j][c] = 0.0f;

    auto load_stage = [&](int s, int kt){
        uint32_t base = sb + (uint32_t)s * (2*G_TILE_B);
        #pragma unroll
        for (int it = 0; it < 8; it++){
            int idx = tid + it*256;
            int isB = idx >> 10;
            int li  = idx & 1023;
            int row = li >> 3;
            int c16 = li & 7;
            const float* src = (isB ? (Bw + (size_t)(bn+row)*K)
                                    : (A  + (size_t)(bm+row)*K)) + kt + c16*4;
            cp_async16(base + (uint32_t)isB*G_TILE_B + (uint32_t)(row*144 + c16*16), src);
        }
        CP_COMMIT();
    };

    #pragma unroll
    for (int s = 0; s < GSTAGES; s++) load_stage(s, s*GKC);

    const int NCH = K / GKC;
    int s = 0;
    for (int ch = 0; ch < NCH; ch++){
        CP_WAIT(GSTAGES-1);
        __syncthreads();

        const float* As = dsm + (size_t)s*2*G_TILE_F;
        const float* Bs = As + G_TILE_F;
        const float* Awp = As + (wm*64 + g)*G_STRIDE + t;
        const float* Bwp = Bs + (wn*32 + g)*G_STRIDE + t;

        #pragma unroll
        for (int ks = 0; ks < 4; ks++){
            int k0 = ks*8;
            uint32_t b[4][2];
            #pragma unroll
            for (int fj = 0; fj < 4; fj++){
                const float* bp = Bwp + fj*8*G_STRIDE + k0;
                b[fj][0] = tf32_bits(bp[0]);
                b[fj][1] = tf32_bits(bp[4]);
            }
            #pragma unroll
            for (int fi = 0; fi < 4; fi++){
                const float* ap = Awp + fi*16*G_STRIDE + k0;
                uint32_t a[4];
                a[0] = tf32_bits(ap[0]);
                a[1] = tf32_bits(ap[8*G_STRIDE]);
                a[2] = tf32_bits(ap[4]);
                a[3] = tf32_bits(ap[8*G_STRIDE+4]);
                #pragma unroll
                for (int fj = 0; fj < 4; fj++)
                    MMA16N8K8(acc[fi][fj], a, b[fj]);
            }
        }
        __syncthreads();
        if (ch + GSTAGES < NCH) load_stage(s, (ch + GSTAGES)*GKC);
        if (++s == GSTAGES) s = 0;
    }

    #pragma unroll
    for (int fi = 0; fi < 4; fi++){
        int m0 = bm + wm*64 + fi*16 + g;
        #pragma unroll
        for (int fj = 0; fj < 4; fj++){
            int n = bn + wn*32 + fj*8 + 2*t;
            float2 bv = *(const float2*)(bias + n);
            float2 o0, o1;
            o0.x = acc[fi][fj][0] + bv.x; o0.y = acc[fi][fj][1] + bv.y;
            o1.x = acc[fi][fj][2] + bv.x; o1.y = acc[fi][fj][3] + bv.y;
            if (EPI == 0){
                o0.x = silu_f(o0.x); o0.y = silu_f(o0.y);
                o1.x = silu_f(o1.x); o1.y = silu_f(o1.y);
            } else {
                float2 r0 = *(const float2*)(resid + (size_t)m0*N + n);
                float2 r1 = *(const float2*)(resid + (size_t)(m0+8)*N + n);
                o0.x += r0.x; o0.y += r0.y;
                o1.x += r1.x; o1.y += r1.y;
            }
            *(float2*)(C + (size_t)m0*N + n)     = o0;
            *(float2*)(C + (size_t)(m0+8)*N + n) = o1;
        }
    }
}

// ---------------- 3. RoPE + gates + head transpose (tf32 pre-round) ----------------
__global__ void rope_gate_kernel(const float* __restrict__ qg,
                                 const float* __restrict__ kg,
                                 const float* __restrict__ vg)
{
    int tid = blockIdx.x * blockDim.x + threadIdx.x;
    int d  = tid & 31;
    int hh = (tid >> 5) & 15;
    int l  = (tid >> 9) & 2047;
    int b  = tid >> 20;
    if (b >= NB) return;
    size_t row   = (size_t)b*NL + l;
    size_t hbase = row * HID;
    float p   = g_pos[row];
    float inv = expf(-(float)d * (9.210340371976184f / 32.0f));
    float fr  = p * inv;
    float sn, cs;
    sincosf(fr, &sn, &cs);
    size_t ob = (((size_t)b*NH + hh)*NL + l)*NDH;
    {
        float2 e = *(const float2*)(&g_h[hbase + 2*ND + hh*NDH + 2*d]);
        float gq = qg[row*NH + hh];
        g_q[ob + d]      = tf32_rnd((e.x*cs - e.y*sn) * gq);
        g_q[ob + d + 32] = tf32_rnd((e.x*sn + e.y*cs) * gq);
    }
    {
        float2 e = *(const float2*)(&g_h[hbase + 3*ND + hh*NDH + 2*d]);
        float gk = kg[row*NH + hh];
        g_k[ob + d]      = tf32_rnd((e.x*cs - e.y*sn) * gk);
        g_k[ob + d + 32] = tf32_rnd((e.x*sn + e.y*cs) * gk);
    }
    {
        float gv = vg[row*NH + hh];
        g_v[ob + d]      = tf32_rnd(g_h[hbase + ND + hh*NDH + d]      * gv);
        g_v[ob + d + 32] = tf32_rnd(g_h[hbase + ND + hh*NDH + d + 32] * gv);
    }
}

// ---------------- 4. tf32 mma attention (R9 base + pair-scoped S barrier) ----------------
// CTA: 64 q-rows for one (b,h); 8 warps. 4-slot KV ring, 3-ahead prefetch.
// QK^T: warp w -> m-rows (w>>1)*16, key-half (w&1)*16. Q frags in regs.
// S@V : same m-rows, d-half (w&1)*32. S round-trip synced per warp PAIR (bar.sync).
#define AST 68
#define SST 36
#define ABK 32
#define A_KV_F (2*ABK*AST)                 // floats per KV slot
#define A_QS_F (64*AST)                    // Q region (>= 64*SST S region)
#define A_SMEM_BYTES ((A_QS_F + 4*A_KV_F)*4)   // 87040

__global__ void __launch_bounds__(256, 2)
attn_mma(const float* __restrict__ bias, const float* __restrict__ head_scale)
{
    extern __shared__ float sm[];
    float* Qs = sm;                    // [64][AST], later reused as Ss [64][SST]
    float* Ss = sm;
    float* KV = sm + A_QS_F;           // [4][{K,V}][ABK][AST]

    const int ib = (int)gridDim.x - 1 - (int)blockIdx.x;   // big tiles first
    const int bh = blockIdx.y;
    const int b  = bh >> 4, hh = bh & 15;
    const int tid = threadIdx.x, lane = tid & 31, wid = tid >> 5;
    const int g = lane >> 2, t = lane & 3;
    const int r0 = (wid >> 1) * 16;        // warp m-rows
    const int kh = (wid & 1);              // key-half / d-half selector
    const int pair_bar = 1 + (wid >> 1);   // named barrier per warp pair

    const int njb = 2*(ib + 1);

    auto load_kv = [&](int slot, int jb){
        if (jb < njb){
            float* Ks = KV + slot*A_KV_F;
            float* Vs = Ks + ABK*AST;
            const float* kp = g_k + ((size_t)bh*NL + (size_t)jb*ABK)*NDH;
            const float* vp = g_v + ((size_t)bh*NL + (size_t)jb*ABK)*NDH;
            #pragma unroll
            for (int it = 0; it < 4; it++){
                int idx = tid + it*256;      // 0..1023
                int isV = idx >> 9;
                int li  = idx & 511;
                int row = li >> 4;
                int c16 = li & 15;
                float* dst = (isV ? Vs : Ks) + row*AST + c16*4;
                const float* src = (isV ? vp : kp) + row*64 + c16*4;
                cp_async16(smem_u32(dst), src);
            }
        }
        CP_COMMIT();
    };

    {   // group 0: Q tile (64 rows x 16 chunks)
        const float* qp = g_q + ((size_t)bh*NL + (size_t)ib*64)*NDH;
        #pragma unroll
        for (int it = 0; it < 4; it++){
            int idx = tid + it*256;
            int row = idx >> 4;
            int c16 = idx & 15;
            cp_async16(smem_u32(Qs + row*AST + c16*4), qp + row*64 + c16*4);
        }
        CP_COMMIT();
    }
    load_kv(0, 0);      // group 1
    load_kv(1, 1);      // group 2
    load_kv(2, 2);      // group 3

    // wait for Q (group0) + slot0 (group1); hoist Q fragments to registers
    CP_WAIT(2);
    __syncthreads();
    uint32_t Qa[8][4];
    {
        const float* qw = Qs + (r0 + g)*AST + t;
        #pragma unroll
        for (int ks = 0; ks < 8; ks++){
            Qa[ks][0] = __float_as_uint(qw[ks*8]);
            Qa[ks][1] = __float_as_uint(qw[8*AST + ks*8]);
            Qa[ks][2] = __float_as_uint(qw[ks*8 + 4]);
            Qa[ks][3] = __float_as_uint(qw[8*AST + ks*8 + 4]);
        }
    }
    __syncthreads();    // all warps done reading Q before S region reuse

    const float scale = head_scale[hh];
    float Yc[4][4];
    #pragma unroll
    for (int j = 0; j < 4; j++)
        #pragma unroll
        for (int c = 0; c < 4; c++) Yc[j][c] = 0.0f;

    const int ig0 = ib*64 + r0 + g;

    for (int jb = 0; jb < njb; ++jb){
        int slot = jb & 3;
        CP_WAIT(2);
        __syncthreads();                       // slot ready; prev iter fully done
        load_kv((jb + 3) & 3, jb + 3);         // refill (empty commit if beyond)

        // bias prefetch (latency hidden under QK mma loop)
        float2 pb0[2], pb1[2];
        {
            const float* bp = bias + ((size_t)b*NL + ig0)*NL + jb*ABK + kh*16 + 2*t;
            #pragma unroll
            for (int nf = 0; nf < 2; nf++){
                pb0[nf] = *(const float2*)(bp + nf*8);
                pb1[nf] = *(const float2*)(bp + nf*8 + (size_t)8*NL);
            }
        }

        const float* Ksb = KV + slot*A_KV_F;
        const float* Vsb = Ksb + ABK*AST;

        // ---- S = Q @ K^T  (keys kh*16 .. kh*16+15) ----
        float Sc[2][4];
        #pragma unroll
        for (int nf = 0; nf < 2; nf++)
            #pragma unroll
            for (int c = 0; c < 4; c++) Sc[nf][c] = 0.0f;

        const float* Bw = Ksb + (kh*16 + g)*AST + t;
        #pragma unroll
        for (int ks = 0; ks < 8; ks++){
            #pragma unroll
            for (int nf = 0; nf < 2; nf++){
                uint32_t bf[2];
                bf[0] = __float_as_uint(Bw[nf*8*AST + ks*8]);
                bf[1] = __float_as_uint(Bw[nf*8*AST + ks*8 + 4]);
                MMA16N8K8(Sc[nf], Qa[ks], bf);
            }
        }

        // ---- epilogue: scale + 4*bias + silu + causal -> Ss ----
        #pragma unroll
        for (int nf = 0; nf < 2; nf++){
            int lc = kh*16 + nf*8 + 2*t;
            int jg = jb*ABK + lc;
            float z00 = silu_f(fmaf(Sc[nf][0], scale, 4.0f*pb0[nf].x));
            float z01 = silu_f(fmaf(Sc[nf][1], scale, 4.0f*pb0[nf].y));
            float z10 = silu_f(fmaf(Sc[nf][2], scale, 4.0f*pb1[nf].x));
            float z11 = silu_f(fmaf(Sc[nf][3], scale, 4.0f*pb1[nf].y));
            if (jg     > ig0    ) z00 = 0.0f;
            if (jg + 1 > ig0    ) z01 = 0.0f;
            if (jg     > ig0 + 8) z10 = 0.0f;
            if (jg + 1 > ig0 + 8) z11 = 0.0f;
            float2 s0, s1;
            s0.x = tf32_rnd(z00); s0.y = tf32_rnd(z01);
            s1.x = tf32_rnd(z10); s1.y = tf32_rnd(z11);
            *(float2*)&Ss[(r0+g)*SST + lc]   = s0;
            *(float2*)&Ss[(r0+8+g)*SST + lc] = s1;
        }
        // pair-scoped barrier: only the 2 warps sharing rows r0..r0+15 exchange S
        asm volatile("bar.sync %0, %1;" :: "r"(pair_bar), "r"(64) : "memory");

        // ---- Y += S @ V  (d-cols kh*32 .. kh*32+31) ----
        const float* Aw2 = Ss + (r0 + g)*SST + t;
        #pragma unroll
        for (int ks = 0; ks < 4; ks++){
            uint32_t a[4];
            a[0] = __float_as_uint(Aw2[ks*8]);
            a[1] = __float_as_uint(Aw2[8*SST + ks*8]);
            a[2] = __float_as_uint(Aw2[ks*8 + 4]);
            a[3] = __float_as_uint(Aw2[8*SST + ks*8 + 4]);
            #pragma unroll
            for (int nf = 0; nf < 4; nf++){
                int dc = kh*32 + nf*8 + g;
                uint32_t bf[2];
                bf[0] = __float_as_uint(Vsb[(ks*8 + t)*AST + dc]);
                bf[1] = __float_as_uint(Vsb[(ks*8 + t + 4)*AST + dc]);
                MMA16N8K8(Yc[nf], a, bf);
            }
        }
    }

    // ---- final: ym = Y * u ----
    {
        int l = ib*64 + r0 + g;
        size_t row0 = (size_t)b*NL + l;
        #pragma unroll
        for (int nf = 0; nf < 4; nf++){
            int d0 = kh*32 + nf*8 + 2*t;
            float2 u0 = *(const float2*)&g_h[row0*HID + hh*NDH + d0];
            float2 u1 = *(const float2*)&g_h[(row0+8)*HID + hh*NDH + d0];
            float2 o0, o1;
            o0.x = Yc[nf][0]*u0.x; o0.y = Yc[nf][1]*u0.y;
            o1.x = Yc[nf][2]*u1.x; o1.y = Yc[nf][3]*u1.y;
            *(float2*)&g_ym[row0*ND + hh*NDH + d0]     = o0;
            *(float2*)&g_ym[(row0+8)*ND + hh*NDH + d0] = o1;
        }
    }
}

// ---------------- 6. LayerNorm ----------------
__global__ void ln_kernel(const float* __restrict__ z, const float* __restrict__ gamma,
                          const float* __restrict__ beta, float* __restrict__ out)
{
    __shared__ float rs[8], rq[8], mv[2];
    int row = blockIdx.x;
    int t = threadIdx.x;
    const float4* zr = (const float4*)(z + (size_t)row * ND);
    float4 v = zr[t];
    float s  = v.x + v.y + v.z + v.w;
    float sq = v.x*v.x + v.y*v.y + v.z*v.z + v.w*v.w;
    #pragma unroll
    for (int o = 16; o; o >>= 1){
        s  += __shfl_down_sync(0xffffffffu, s,  o);
        sq += __shfl_down_sync(0xffffffffu, sq, o);
    }
    if ((t & 31) == 0){ rs[t>>5] = s; rq[t>>5] = sq; }
    __syncthreads();
    if (t == 0){
        float S = 0.f, Q = 0.f;
        #pragma unroll
        for (int i = 0; i < 8; i++){ S += rs[i]; Q += rq[i]; }
        float mean = S * (1.0f/ND);
        float var  = Q * (1.0f/ND) - mean*mean;
        mv[0] = mean; mv[1] = rsqrtf(var + 1e-5f);
    }
    __syncthreads();
    float mean = mv[0], rstd = mv[1];
    float4 g  = ((const float4*)gamma)[t];
    float4 be = ((const float4*)beta )[t];
    float4 o;
    o.x = (v.x - mean)*rstd*g.x + be.x;
    o.y = (v.y - mean)*rstd*g.y + be.y;
    o.z = (v.z - mean)*rstd*g.z + be.z;
    o.w = (v.w - mean)*rstd*g.w + be.w;
    ((float4*)(out + (size_t)row * ND))[t] = o;
}

// ---------------- launch ----------------
extern "C" void kernel_launch(void* const* d_in, const int* in_sizes, int n_in,
                              void* d_out, int out_size)
{
    const float* x   = (const float*)d_in[0];
    const float* rl  = (const float*)d_in[3];
    const float* qg  = (const float*)d_in[4];
    const float* kg  = (const float*)d_in[5];
    const float* vg  = (const float*)d_in[6];
    const float* tpb = (const float*)d_in[7];
    const float* pw  = (const float*)d_in[8];
    const float* pb  = (const float*)d_in[9];
    const float* ow  = (const float*)d_in[10];
    const float* ob  = (const float*)d_in[11];
    const float* hs  = (const float*)d_in[12];
    const float* lg  = (const float*)d_in[13];
    const float* lb  = (const float*)d_in[14];
    float* out = (float*)d_out;

    float *hp, *ymp, *zp;
    cudaGetSymbolAddress((void**)&hp,  g_h);
    cudaGetSymbolAddress((void**)&ymp, g_ym);
    cudaGetSymbolAddress((void**)&zp,  g_z);

    cudaFuncSetAttribute(gemm_mma<0>, cudaFuncAttributeMaxDynamicSharedMemorySize, G_SMEM_BYTES);
    cudaFuncSetAttribute(gemm_mma<1>, cudaFuncAttributeMaxDynamicSharedMemorySize, G_SMEM_BYTES);
    cudaFuncSetAttribute(attn_mma,    cudaFuncAttributeMaxDynamicSharedMemorySize, A_SMEM_BYTES);

    // 1. positions
    cumsum_kernel<<<NB, 1024>>>(rl);

    // 2. h = silu(x @ proj_w^T + proj_b)   [tf32 mma]
    gemm_mma<0><<<dim3(HID/128, MROWS/128), 256, G_SMEM_BYTES>>>(x, pw, pb, nullptr, hp, HID, ND);

    // 3. rope + gates + head transpose (+ tf32 pre-round of q/k/v)
    rope_gate_kernel<<<(NB*NL*NH*32)/256, 256>>>(qg, kg, vg);

    // 4. fused attention + u-gate   [tf32 mma]
    attn_mma<<<dim3(NL/64, NB*NH), 256, A_SMEM_BYTES>>>(tpb, hs);

    // 5. z = ym @ out_w^T + out_b + x   [tf32 mma]
    gemm_mma<1><<<dim3(ND/128, MROWS/128), 256, G_SMEM_BYTES>>>(ymp, ow, ob, x, zp, ND, ND);

    // 6. layernorm
    ln_kernel<<<MROWS, 256>>>(zp, lg, lb, out);
}